// round 1
// baseline (speedup 1.0000x reference)
#include <cuda_runtime.h>
#include <cstdint>

#define M_ROWS 128
#define N_COLS 8192
#define K_DIM  8192

#define BM 128
#define BN 64
#define BK 32
#define NK (K_DIM / BK)

// x pre-converted to tf32 bit patterns (stored as float)
__device__ float g_xt[M_ROWS * K_DIM];

__device__ __forceinline__ uint32_t f2tf32(float f) {
    uint32_t u;
    asm("cvt.rna.tf32.f32 %0, %1;" : "=r"(u) : "f"(f));
    return u;
}

__global__ void convert_x_kernel(const float* __restrict__ x) {
    int i = blockIdx.x * blockDim.x + threadIdx.x;   // float4 index, grid covers exactly M*K/4
    float4 v = reinterpret_cast<const float4*>(x)[i];
    uint4 o;
    o.x = f2tf32(v.x);
    o.y = f2tf32(v.y);
    o.z = f2tf32(v.z);
    o.w = f2tf32(v.w);
    reinterpret_cast<uint4*>(g_xt)[i] = o;
}

__device__ __forceinline__ void mma_tf32(float* d, const uint32_t* a, const uint32_t* b) {
    asm volatile(
        "mma.sync.aligned.m16n8k8.row.col.f32.tf32.tf32.f32 "
        "{%0,%1,%2,%3},{%4,%5,%6,%7},{%8,%9},{%0,%1,%2,%3};\n"
        : "+f"(d[0]), "+f"(d[1]), "+f"(d[2]), "+f"(d[3])
        : "r"(a[0]), "r"(a[1]), "r"(a[2]), "r"(a[3]), "r"(b[0]), "r"(b[1]));
}

// out[m,n] = sum_k x[m,k] * (W[n,k] + 2*s*B[n%16]*A[n/16,k])
__global__ __launch_bounds__(256, 1)
void lokr_gemm_kernel(const float* __restrict__ Wm,
                      const float* __restrict__ Am,
                      const float* __restrict__ Bv,
                      const float* __restrict__ sc,
                      float* __restrict__ out)
{
    // XOR-swizzled tiles: element (r, k) lives at r*BK + (k ^ 4*(r&7))
    __shared__ float xs[2][BM * BK];   // 32 KB
    __shared__ float ws[2][BN * BK];   // 16 KB

    const int t    = threadIdx.x;
    const int lane = t & 31;
    const int warp = t >> 5;
    const int wr   = warp & 3;   // m-warp 0..3 (32 rows each)
    const int wcn  = warp >> 2;  // n-warp 0..1 (32 cols each)
    const int n0   = blockIdx.x * BN;

    // LoKr fused correction scalar for this thread's W rows.
    // Thread t owns W rows (n0 + t/8) and (n0 + t/8 + 32); both have the same n%16.
    const float bb = 2.0f * sc[0] * Bv[(t >> 3) & 15];

    const int kq  = t & 7;        // float4 column within BK=32
    const int row = t >> 3;       // 0..31
    const int sw  = 4 * (kq ^ (row & 7));      // swizzled float col (same for row, row+32, ...)
    const int sbase = row * BK + sw;

    const float* xg = g_xt + (size_t)row * K_DIM + kq * 4;
    const float* wg = Wm + (size_t)(n0 + row) * K_DIM + kq * 4;
    const float* ag = Am + (size_t)((n0 + row) >> 4) * K_DIM + kq * 4;

    float4 xr[4];
    float4 wcv[2];

    // ---- prologue: load k-tile 0 ----
    #pragma unroll
    for (int j = 0; j < 4; ++j)
        xr[j] = *reinterpret_cast<const float4*>(xg + (size_t)(32 * j) * K_DIM);
    {
        float4 w0 = __ldcs(reinterpret_cast<const float4*>(wg));
        float4 w1 = __ldcs(reinterpret_cast<const float4*>(wg + (size_t)32 * K_DIM));
        float4 a0 = *reinterpret_cast<const float4*>(ag);
        float4 a1 = *reinterpret_cast<const float4*>(ag + (size_t)2 * K_DIM);
        wcv[0].x = __uint_as_float(f2tf32(fmaf(bb, a0.x, w0.x)));
        wcv[0].y = __uint_as_float(f2tf32(fmaf(bb, a0.y, w0.y)));
        wcv[0].z = __uint_as_float(f2tf32(fmaf(bb, a0.z, w0.z)));
        wcv[0].w = __uint_as_float(f2tf32(fmaf(bb, a0.w, w0.w)));
        wcv[1].x = __uint_as_float(f2tf32(fmaf(bb, a1.x, w1.x)));
        wcv[1].y = __uint_as_float(f2tf32(fmaf(bb, a1.y, w1.y)));
        wcv[1].z = __uint_as_float(f2tf32(fmaf(bb, a1.z, w1.z)));
        wcv[1].w = __uint_as_float(f2tf32(fmaf(bb, a1.w, w1.w)));
    }
    {
        float* dx = &xs[0][sbase];
        #pragma unroll
        for (int j = 0; j < 4; ++j)
            *reinterpret_cast<float4*>(dx + j * 32 * BK) = xr[j];
        float* dw = &ws[0][sbase];
        *reinterpret_cast<float4*>(dw) = wcv[0];
        *reinterpret_cast<float4*>(dw + 32 * BK) = wcv[1];
    }
    __syncthreads();

    float acc[2][4][4];
    #pragma unroll
    for (int mt = 0; mt < 2; ++mt)
        #pragma unroll
        for (int nt = 0; nt < 4; ++nt)
            #pragma unroll
            for (int r = 0; r < 4; ++r)
                acc[mt][nt][r] = 0.0f;

    const int q = lane & 3;
    const int g = lane >> 2;

    int buf = 0;
    for (int kt = 0; kt < NK; ++kt) {
        const bool has = (kt + 1) < NK;
        if (has) {
            xg += BK; wg += BK; ag += BK;
            #pragma unroll
            for (int j = 0; j < 4; ++j)
                xr[j] = *reinterpret_cast<const float4*>(xg + (size_t)(32 * j) * K_DIM);
            float4 w0 = __ldcs(reinterpret_cast<const float4*>(wg));
            float4 w1 = __ldcs(reinterpret_cast<const float4*>(wg + (size_t)32 * K_DIM));
            float4 a0 = *reinterpret_cast<const float4*>(ag);
            float4 a1 = *reinterpret_cast<const float4*>(ag + (size_t)2 * K_DIM);
            wcv[0].x = __uint_as_float(f2tf32(fmaf(bb, a0.x, w0.x)));
            wcv[0].y = __uint_as_float(f2tf32(fmaf(bb, a0.y, w0.y)));
            wcv[0].z = __uint_as_float(f2tf32(fmaf(bb, a0.z, w0.z)));
            wcv[0].w = __uint_as_float(f2tf32(fmaf(bb, a0.w, w0.w)));
            wcv[1].x = __uint_as_float(f2tf32(fmaf(bb, a1.x, w1.x)));
            wcv[1].y = __uint_as_float(f2tf32(fmaf(bb, a1.y, w1.y)));
            wcv[1].z = __uint_as_float(f2tf32(fmaf(bb, a1.z, w1.z)));
            wcv[1].w = __uint_as_float(f2tf32(fmaf(bb, a1.w, w1.w)));
        }

        // ---- compute on current buffer ----
        const float* xb = xs[buf];
        const float* wb = ws[buf];
        #pragma unroll
        for (int kg = 0; kg < 4; ++kg) {
            const int c0 = (kg * 8 + q)     ^ (g * 4);
            const int c1 = (kg * 8 + q + 4) ^ (g * 4);
            uint32_t afr[2][4];
            #pragma unroll
            for (int mt = 0; mt < 2; ++mt) {
                const float* base = xb + (wr * 32 + mt * 16 + g) * BK;
                afr[mt][0] = __float_as_uint(base[c0]);
                afr[mt][1] = __float_as_uint(base[8 * BK + c0]);
                afr[mt][2] = __float_as_uint(base[c1]);
                afr[mt][3] = __float_as_uint(base[8 * BK + c1]);
            }
            uint32_t bfr[4][2];
            #pragma unroll
            for (int nt = 0; nt < 4; ++nt) {
                const float* base = wb + (wcn * 32 + nt * 8 + g) * BK;
                bfr[nt][0] = __float_as_uint(base[c0]);
                bfr[nt][1] = __float_as_uint(base[c1]);
            }
            #pragma unroll
            for (int mt = 0; mt < 2; ++mt)
                #pragma unroll
                for (int nt = 0; nt < 4; ++nt)
                    mma_tf32(acc[mt][nt], afr[mt], bfr[nt]);
        }

        if (has) {
            float* dx = &xs[buf ^ 1][sbase];
            #pragma unroll
            for (int j = 0; j < 4; ++j)
                *reinterpret_cast<float4*>(dx + j * 32 * BK) = xr[j];
            float* dw = &ws[buf ^ 1][sbase];
            *reinterpret_cast<float4*>(dw) = wcv[0];
            *reinterpret_cast<float4*>(dw + 32 * BK) = wcv[1];
        }
        __syncthreads();
        buf ^= 1;
    }

    // ---- epilogue ----
    #pragma unroll
    for (int mt = 0; mt < 2; ++mt) {
        #pragma unroll
        for (int nt = 0; nt < 4; ++nt) {
            const int m = wr * 32 + mt * 16 + g;
            const int n = n0 + wcn * 32 + nt * 8 + q * 2;
            float2 v0 = make_float2(acc[mt][nt][0], acc[mt][nt][1]);
            float2 v1 = make_float2(acc[mt][nt][2], acc[mt][nt][3]);
            *reinterpret_cast<float2*>(out + (size_t)m * N_COLS + n) = v0;
            *reinterpret_cast<float2*>(out + (size_t)(m + 8) * N_COLS + n) = v1;
        }
    }
}

extern "C" void kernel_launch(void* const* d_in, const int* in_sizes, int n_in,
                              void* d_out, int out_size) {
    const float* x  = (const float*)d_in[0];   // (128, 8192)
    const float* Wm = (const float*)d_in[1];   // (8192, 8192)
    const float* Am = (const float*)d_in[2];   // (512, 8192)
    const float* Bv = (const float*)d_in[3];   // (16, 1)
    const float* sc = (const float*)d_in[4];   // (1,)
    float* out = (float*)d_out;                // (128, 8192)

    convert_x_kernel<<<(M_ROWS * K_DIM / 4) / 256, 256>>>(x);
    lokr_gemm_kernel<<<N_COLS / BN, 256>>>(Wm, Am, Bv, sc, out);
}

// round 3
// speedup vs baseline: 1.2030x; 1.2030x over previous
#include <cuda_runtime.h>
#include <cstdint>

#define K_DIM  8192
#define M_ROWS 128
#define N_COLS 8192
#define BN     64
#define BK     64
#define NK     (K_DIM / BK)    // 128
#define NBUF   4

// shared-memory layout in floats
#define XS_FL  (M_ROWS * BK)                 // 8192 per stage
#define WS_FL  (BN * BK)                     // 4096 per stage
#define AS_FL  (8 * BK)                      // 512 per stage
#define XS_OFF 0
#define WS_OFF (NBUF * XS_FL)                // 32768
#define AS_OFF (WS_OFF + NBUF * WS_FL)       // 49152
#define SMEM_FLOATS (AS_OFF + NBUF * AS_FL)  // 51200 floats = 204800 B

__device__ float g_xt[M_ROWS * K_DIM];   // x, tf32 round-to-nearest

__device__ __forceinline__ uint32_t f2tf32(float f) {
    uint32_t u;
    asm("cvt.rna.tf32.f32 %0, %1;" : "=r"(u) : "f"(f));
    return u;
}

__device__ __forceinline__ uint32_t smem_u32(const void* p) {
    uint32_t a;
    asm("{ .reg .u64 t; cvta.to.shared.u64 t, %1; cvt.u32.u64 %0, t; }" : "=r"(a) : "l"(p));
    return a;
}

__device__ __forceinline__ void cp16(uint32_t dst, const void* src) {
    asm volatile("cp.async.cg.shared.global [%0], [%1], 16;" :: "r"(dst), "l"(src));
}

__device__ __forceinline__ void mma_tf32(float* d, const uint32_t* a, const uint32_t* b) {
    asm volatile(
        "mma.sync.aligned.m16n8k8.row.col.f32.tf32.tf32.f32 "
        "{%0,%1,%2,%3},{%4,%5,%6,%7},{%8,%9},{%0,%1,%2,%3};\n"
        : "+f"(d[0]), "+f"(d[1]), "+f"(d[2]), "+f"(d[3])
        : "r"(a[0]), "r"(a[1]), "r"(a[2]), "r"(a[3]), "r"(b[0]), "r"(b[1]));
}

__global__ void cvt_x_kernel(const float* __restrict__ x) {
    int i = blockIdx.x * blockDim.x + threadIdx.x;
    float4 v = reinterpret_cast<const float4*>(x)[i];
    uint4 o;
    o.x = f2tf32(v.x); o.y = f2tf32(v.y); o.z = f2tf32(v.z); o.w = f2tf32(v.w);
    reinterpret_cast<uint4*>(g_xt)[i] = o;
}

// out[m,n] = sum_k x[m,k]*W[n,k]  +  2*s*B[n%16] * (x @ A^T)[m, n/16]
__global__ __launch_bounds__(256, 1)
void lokr_gemm_kernel(const float* __restrict__ Wm,
                      const float* __restrict__ Am,
                      const float* __restrict__ Bv,
                      const float* __restrict__ sc,
                      float* __restrict__ out)
{
    extern __shared__ float sm[];
    const uint32_t sb = smem_u32(sm);

    const int t    = threadIdx.x;
    const int lane = t & 31;
    const int warp = t >> 5;
    const int wr   = warp & 3;     // m-warp (32 rows)
    const int wcn  = warp >> 2;    // n-warp (32 cols)
    const int q    = lane & 3;
    const int g    = lane >> 2;
    const int n0   = blockIdx.x * BN;

    const int kq = t & 7;          // 16B chunk in a 32-float half-row
    const int rr = t >> 3;         // 0..31
    const uint32_t swc = (uint32_t)((kq ^ (rr & 7)) << 4);   // swizzled byte offset

    // zero the A-subtile pad rows (4..7) for every stage/half — written once, never touched
    for (int i = t; i < NBUF * 2 * 4 * 32; i += 256) {
        const int s = i >> 8;
        const int r = i & 255;
        const int h = r >> 7;
        const int rw = 4 + ((r >> 5) & 3);
        const int c = r & 31;
        sm[AS_OFF + s * AS_FL + h * 256 + rw * 32 + c] = 0.0f;
    }

    const float* xg = g_xt + (size_t)rr * K_DIM + kq * 4;
    const float* wg = Wm + (size_t)(n0 + rr) * K_DIM + kq * 4;

    // ---- W register ring: 2 stages deep ----
    float4 wreg[2][4];
    #pragma unroll
    for (int slot = 0; slot < 2; ++slot)
        #pragma unroll
        for (int jm = 0; jm < 2; ++jm)
            #pragma unroll
            for (int h = 0; h < 2; ++h)
                wreg[slot][jm * 2 + h] = __ldcs(reinterpret_cast<const float4*>(
                    wg + (size_t)(32 * jm) * K_DIM + slot * BK + h * 32));

    auto fill = [&](int f) {
        const int s = f & 3;
        // W: cvt.rna.tf32 -> STS from ring slot (loaded 2 stages earlier)
        float4* wrp = wreg[f & 1];
        #pragma unroll
        for (int jm = 0; jm < 2; ++jm) {
            #pragma unroll
            for (int h = 0; h < 2; ++h) {
                float4 v = wrp[jm * 2 + h];
                uint4 c;
                c.x = f2tf32(v.x); c.y = f2tf32(v.y); c.z = f2tf32(v.z); c.w = f2tf32(v.w);
                const uint32_t wd = sb + 4u * (WS_OFF + s * WS_FL + h * 2048 + (32 * jm + rr) * 32) + swc;
                asm volatile("st.shared.v4.b32 [%0], {%1,%2,%3,%4};"
                             :: "r"(wd), "r"(c.x), "r"(c.y), "r"(c.z), "r"(c.w));
            }
        }
        // refill ring for stage f+2
        if (f + 2 < NK) {
            const float* p = wg + (size_t)(f + 2) * BK;
            #pragma unroll
            for (int jm = 0; jm < 2; ++jm)
                #pragma unroll
                for (int h = 0; h < 2; ++h)
                    wrp[jm * 2 + h] = __ldcs(reinterpret_cast<const float4*>(
                        p + (size_t)(32 * jm) * K_DIM + h * 32));
        }
        // x tile via cp.async (L2-hot, pre-converted tf32)
        #pragma unroll
        for (int h = 0; h < 2; ++h)
            #pragma unroll
            for (int j = 0; j < 4; ++j) {
                const uint32_t xd = sb + 4u * (XS_OFF + s * XS_FL + h * 4096 + (32 * j + rr) * 32) + swc;
                cp16(xd, xg + (size_t)(32 * j) * K_DIM + (size_t)f * BK + h * 32);
            }
        // A rows (4 real rows) via cp.async, raw fp32 (HW truncates to tf32; correction term only)
        if (t < 64) {
            const int ar = t >> 4;
            const int kk = t & 15;
            const int h = kk >> 3;
            const int kq3 = kk & 7;
            const uint32_t swa = (uint32_t)((kq3 ^ ar) << 4);
            const uint32_t ad = sb + 4u * (AS_OFF + s * AS_FL + h * 256 + ar * 32) + swa;
            cp16(ad, Am + (size_t)(blockIdx.x * 4 + ar) * K_DIM + (size_t)f * BK + h * 32 + kq3 * 4);
        }
        asm volatile("cp.async.commit_group;");
    };

    fill(0);
    fill(1);

    float acc[2][4][4];
    float yac[2][4];
    #pragma unroll
    for (int mt = 0; mt < 2; ++mt) {
        #pragma unroll
        for (int nt = 0; nt < 4; ++nt)
            #pragma unroll
            for (int r = 0; r < 4; ++r) acc[mt][nt][r] = 0.0f;
        #pragma unroll
        for (int r = 0; r < 4; ++r) yac[mt][r] = 0.0f;
    }

    for (int kt = 0; kt < NK; ++kt) {
        if (kt + 2 < NK) {
            fill(kt + 2);
            asm volatile("cp.async.wait_group 2;");
        } else if (kt + 1 < NK) {
            asm volatile("cp.async.wait_group 1;");
        } else {
            asm volatile("cp.async.wait_group 0;");
        }
        __syncthreads();

        const int s = kt & 3;
        const float* xb0 = sm + XS_OFF + s * XS_FL;
        const float* wb0 = sm + WS_OFF + s * WS_FL;
        const float* ab0 = sm + AS_OFF + s * AS_FL;

        #pragma unroll
        for (int h = 0; h < 2; ++h) {
            const float* xb = xb0 + h * 4096;
            const float* wb = wb0 + h * 2048;
            const float* ab = ab0 + h * 256;
            #pragma unroll
            for (int kg = 0; kg < 4; ++kg) {
                const int c0 = (kg * 8 + q) ^ (g * 4);
                const int c1 = c0 ^ 4;
                uint32_t afr[2][4];
                #pragma unroll
                for (int mt = 0; mt < 2; ++mt) {
                    const float* base = xb + (wr * 32 + mt * 16 + g) * 32;
                    afr[mt][0] = __float_as_uint(base[c0]);
                    afr[mt][1] = __float_as_uint(base[8 * 32 + c0]);
                    afr[mt][2] = __float_as_uint(base[c1]);
                    afr[mt][3] = __float_as_uint(base[8 * 32 + c1]);
                }
                uint32_t bfr[4][2];
                #pragma unroll
                for (int nt = 0; nt < 4; ++nt) {
                    const float* base = wb + (wcn * 32 + nt * 8 + g) * 32;
                    bfr[nt][0] = __float_as_uint(base[c0]);
                    bfr[nt][1] = __float_as_uint(base[c1]);
                }
                uint32_t bex[2];
                {
                    const float* base = ab + g * 32;
                    bex[0] = __float_as_uint(base[c0]);
                    bex[1] = __float_as_uint(base[c1]);
                }
                #pragma unroll
                for (int mt = 0; mt < 2; ++mt) {
                    #pragma unroll
                    for (int nt = 0; nt < 4; ++nt)
                        mma_tf32(acc[mt][nt], afr[mt], bfr[nt]);
                    mma_tf32(yac[mt], afr[mt], bex);
                }
            }
        }
    }

    // ---- epilogue: out = acc + cf[n%16] * y[m, n/16] ----
    const float s2 = 2.0f * sc[0];
    const float cfe0 = s2 * Bv[2 * q];
    const float cfe1 = s2 * Bv[2 * q + 1];
    const float cfo0 = s2 * Bv[8 + 2 * q];
    const float cfo1 = s2 * Bv[9 + 2 * q];

    #pragma unroll
    for (int mt = 0; mt < 2; ++mt) {
        const int srcl = g * 4 + wcn;
        const float yA0 = __shfl_sync(0xFFFFFFFFu, yac[mt][0], srcl);
        const float yA1 = __shfl_sync(0xFFFFFFFFu, yac[mt][1], srcl);
        const float yB0 = __shfl_sync(0xFFFFFFFFu, yac[mt][2], srcl);
        const float yB1 = __shfl_sync(0xFFFFFFFFu, yac[mt][3], srcl);
        #pragma unroll
        for (int nt = 0; nt < 4; ++nt) {
            const float yg  = (nt < 2) ? yA0 : yA1;
            const float yg8 = (nt < 2) ? yB0 : yB1;
            const float f0 = (nt & 1) ? cfo0 : cfe0;
            const float f1 = (nt & 1) ? cfo1 : cfe1;
            const int m = wr * 32 + mt * 16 + g;
            const int n = n0 + wcn * 32 + nt * 8 + 2 * q;
            float2 v0 = make_float2(acc[mt][nt][0] + f0 * yg, acc[mt][nt][1] + f1 * yg);
            float2 v1 = make_float2(acc[mt][nt][2] + f0 * yg8, acc[mt][nt][3] + f1 * yg8);
            *reinterpret_cast<float2*>(out + (size_t)m * N_COLS + n) = v0;
            *reinterpret_cast<float2*>(out + (size_t)(m + 8) * N_COLS + n) = v1;
        }
    }
}

extern "C" void kernel_launch(void* const* d_in, const int* in_sizes, int n_in,
                              void* d_out, int out_size) {
    const float* x  = (const float*)d_in[0];   // (128, 8192)
    const float* Wm = (const float*)d_in[1];   // (8192, 8192)
    const float* Am = (const float*)d_in[2];   // (512, 8192)
    const float* Bv = (const float*)d_in[3];   // (16, 1)
    const float* sc = (const float*)d_in[4];   // (1,)
    float* out = (float*)d_out;                // (128, 8192)

    cudaFuncSetAttribute(lokr_gemm_kernel,
                         cudaFuncAttributeMaxDynamicSharedMemorySize,
                         SMEM_FLOATS * 4);

    cvt_x_kernel<<<(M_ROWS * K_DIM / 4) / 256, 256>>>(x);
    lokr_gemm_kernel<<<N_COLS / BN, 256, SMEM_FLOATS * 4>>>(Wm, Am, Bv, sc, out);
}